// round 16
// baseline (speedup 1.0000x reference)
#include <cuda_runtime.h>
#include <cuda_bf16.h>
#include <cstdint>

// SupConLoss N=8192, D=128, T=0.1 — mma.sync bf16 (sm_103 base target).
// R16 = R14 (symmetric single-tile CTAs, measured 57.9us) + last-CTA fused
// finish. R15's tile-pairing reverted: 3 inlined MMA+epilogue bodies spilled
// registers under the 128-reg cap and regressed 32us.

static constexpr int NN = 8192;
static constexpr int DD = 128;
static constexpr int TB = 128;            // tile dim
static constexpr int NT = NN / TB;        // 64
static constexpr int NTILES = NT * (NT / 2) + NT / 2; // 2080

__device__ __align__(16) __nv_bfloat16 g_featbf[NN * DD];
__device__ float g_sumexp[NN];
__device__ float g_possum[NN];
__device__ int   g_lab[NN];
__device__ int   g_hist[1024];
__device__ int   g_is64;
__device__ int   g_done;

// ---------------- PTX helpers (base-target only) -----------------------------
__device__ __forceinline__ uint32_t smem_u32(const void* p) {
    uint32_t a;
    asm("{ .reg .u64 t; cvta.to.shared.u64 t, %1; cvt.u32.u64 %0, t; }"
        : "=r"(a) : "l"(p));
    return a;
}
#define LDSM4(r0, r1, r2, r3, addr) \
    asm volatile("ldmatrix.sync.aligned.m8n8.x4.shared.b16 {%0,%1,%2,%3}, [%4];" \
        : "=r"(r0), "=r"(r1), "=r"(r2), "=r"(r3) : "r"(addr))
#define MMA16816(d, a0, a1, a2, a3, b0, b1) \
    asm volatile("mma.sync.aligned.m16n8k16.row.col.f32.bf16.bf16.f32 " \
        "{%0,%1,%2,%3}, {%4,%5,%6,%7}, {%8,%9}, {%0,%1,%2,%3};" \
        : "+f"((d)[0]), "+f"((d)[1]), "+f"((d)[2]), "+f"((d)[3]) \
        : "r"(a0), "r"(a1), "r"(a2), "r"(a3), "r"(b0), "r"(b1))
#define CP_ASYNC16(sdst, gsrc) \
    asm volatile("cp.async.cg.shared.global [%0], [%1], 16;" \
        :: "r"(sdst), "l"(gsrc) : "memory")
#define CP_COMMIT()  asm volatile("cp.async.commit_group;" ::: "memory")
#define CP_WAIT0()   asm volatile("cp.async.wait_group 0;" ::: "memory")

// ---------------------------------------------------------------------------
__global__ void init_kernel(const int* __restrict__ labs, float* out) {
    int gid = blockIdx.x * 256 + threadIdx.x;
    if (gid < NN)   { g_sumexp[gid] = 0.0f; g_possum[gid] = 0.0f; }
    if (gid < 1024) g_hist[gid] = 0;
    if (gid == 0)   { out[0] = 0.0f; g_done = 0; }
    if (blockIdx.x == 0) {
        __shared__ int red[256];
        int tid = threadIdx.x;
        int nz = 0;
        for (int i = tid; i < NN / 2; i += 256) nz |= labs[2 * i + 1];
        red[tid] = nz;
        __syncthreads();
        for (int s = 128; s > 0; s >>= 1) {
            if (tid < s) red[tid] |= red[tid + s];
            __syncthreads();
        }
        if (tid == 0) g_is64 = (red[0] == 0) ? 1 : 0;
    }
}

__global__ void prep_kernel(const float* __restrict__ feats,
                            const void* __restrict__ labels) {
    int row  = blockIdx.x * 8 + (threadIdx.x >> 5);
    int lane = threadIdx.x & 31;
    float4 v = reinterpret_cast<const float4*>(feats)[row * 32 + lane];
    float ss = v.x * v.x + v.y * v.y + v.z * v.z + v.w * v.w;
    #pragma unroll
    for (int o = 16; o > 0; o >>= 1) ss += __shfl_xor_sync(0xffffffffu, ss, o);
    float sc = 1.0f / sqrtf(ss);
    __nv_bfloat162 p0 = __floats2bfloat162_rn(v.x * sc, v.y * sc);
    __nv_bfloat162 p1 = __floats2bfloat162_rn(v.z * sc, v.w * sc);
    uint2 u;
    u.x = *reinterpret_cast<uint32_t*>(&p0);
    u.y = *reinterpret_cast<uint32_t*>(&p1);
    reinterpret_cast<uint2*>(g_featbf)[row * 32 + lane] = u;
    if (lane == 0) {
        int lab = g_is64 ? (int)((const long long*)labels)[row]
                         : ((const int*)labels)[row];
        g_lab[row] = lab;
        atomicAdd(&g_hist[lab & 1023], 1);
    }
}

// ---------------------------------------------------------------------------
// SMEM: A 32KB | B 32KB | col labels 512B | col accumulators 2x512B.
// Rows: 256B K-major, 16B chunks XOR-swizzled with (row & 7).
static constexpr int SM_A   = 0;
static constexpr int SM_B   = 32768;
static constexpr int SM_LJ  = 65536;
static constexpr int SM_CE  = 66048;
static constexpr int SM_CP  = 66560;
static constexpr int SM_TOT = 67072;

__device__ __forceinline__ void cp_tile(uint32_t sdst,
                                        const __nv_bfloat16* gsrc, int tid) {
    #pragma unroll
    for (int i = 0; i < 8; i++) {
        int e   = i * 256 + tid;        // 2048 x 16B
        int row = e >> 4;
        int ch  = e & 15;
        uint32_t off = row * 256 + ((ch ^ (row & 7)) << 4);
        CP_ASYNC16(sdst + off, (const char*)gsrc + (size_t)e * 16);
    }
}

// exp(10*x) = ex2(x * 10*log2(e))
static constexpr float EXSCALE = 14.4269504088896341f;

template <bool DIAG>
__device__ __forceinline__ void epilogue(const float (&acc)[2][8][4],
                                         const int* __restrict__ s_lj,
                                         float* __restrict__ s_ce,
                                         float* __restrict__ s_cp,
                                         int wm, int wn, int lane,
                                         const int (&li)[2][2],
                                         float (&re)[2][2], float (&rp)[2][2]) {
    #pragma unroll
    for (int nt = 0; nt < 8; nt++) {
        int c0  = wn * 64 + nt * 8 + 2 * (lane & 3);
        int lj0 = s_lj[c0], lj1 = s_lj[c0 + 1];
        float ce0 = 0, ce1 = 0, cq0 = 0, cq1 = 0;
        #pragma unroll
        for (int mt = 0; mt < 2; mt++) {
            int r0 = wm * 32 + mt * 16 + (lane >> 2);
            #pragma unroll
            for (int q = 0; q < 4; q++) {
                int   h  = q >> 1;
                float a  = acc[mt][nt][q];
                float x  = a * EXSCALE;
                float e;
                asm("ex2.approx.f32 %0, %1;" : "=f"(e) : "f"(x));
                bool match = (li[mt][h] == ((q & 1) ? lj1 : lj0));
                if (DIAG) {
                    int rl = r0 + h * 8;
                    if (c0 + (q & 1) == rl) { e = 0.0f; match = false; }
                }
                re[mt][h] += e;
                if (match) rp[mt][h] += a;
                if (!DIAG) {
                    if (q & 1) { ce1 += e; if (match) cq1 += a; }
                    else       { ce0 += e; if (match) cq0 += a; }
                }
            }
        }
        if (!DIAG) {
            #pragma unroll
            for (int o = 4; o <= 16; o <<= 1) {
                ce0 += __shfl_xor_sync(0xffffffffu, ce0, o);
                ce1 += __shfl_xor_sync(0xffffffffu, ce1, o);
                cq0 += __shfl_xor_sync(0xffffffffu, cq0, o);
                cq1 += __shfl_xor_sync(0xffffffffu, cq1, o);
            }
            if (lane < 4) {
                int c = wn * 64 + nt * 8 + 2 * lane;
                atomicAdd(&s_ce[c],     ce0);
                atomicAdd(&s_ce[c + 1], ce1);
                atomicAdd(&s_cp[c],     cq0);
                atomicAdd(&s_cp[c + 1], cq1);
            }
        }
    }
}

__global__ void __launch_bounds__(256, 2)
main_kernel(float* __restrict__ out) {
    extern __shared__ char smem[];
    uint32_t sb = smem_u32(smem);
    int tid  = threadIdx.x;
    int wid  = tid >> 5, lane = tid & 31;
    int sub  = lane & 7, g = lane >> 3;
    int wm   = wid & 3, wn = wid >> 2;     // 4x2 warp grid (M x N)

    // tile (bi, bj): d=0..31 for all bi, d=32 for bi<32 (upper triangle, once)
    int idx = blockIdx.x;
    int bi, d;
    if (idx < NT * 32) { bi = idx & (NT - 1); d = idx >> 6; }
    else               { bi = idx - NT * 32; d = 32; }
    int bj = (bi + d) & (NT - 1);
    bool diag = (d == 0);

    cp_tile(sb + SM_A, g_featbf + (size_t)bi * TB * DD, tid);
    if (!diag) cp_tile(sb + SM_B, g_featbf + (size_t)bj * TB * DD, tid);
    if (tid < 32) CP_ASYNC16(sb + SM_LJ + tid * 16,
                             (const char*)(g_lab + bj * TB) + tid * 16);
    CP_COMMIT();

    float* s_ce = reinterpret_cast<float*>(smem + SM_CE);
    float* s_cp = reinterpret_cast<float*>(smem + SM_CP);
    if (tid < 128) { s_ce[tid] = 0.0f; s_cp[tid] = 0.0f; }

    int li[2][2];
    #pragma unroll
    for (int mt = 0; mt < 2; mt++)
        #pragma unroll
        for (int h = 0; h < 2; h++)
            li[mt][h] = g_lab[bi * TB + wm * 32 + mt * 16 + h * 8 + (lane >> 2)];

    int arow = wm * 32 + (g & 1) * 8 + sub;          // + mt*16
    int akx  = g >> 1;
    int brow = wn * 64 + (g >> 1) * 8 + sub;         // + p*16
    int bkx  = g & 1;

    CP_WAIT0();
    __syncthreads();

    uint32_t SA = sb + SM_A;
    uint32_t SB = diag ? SA : (sb + SM_B);
    const int* s_lj = reinterpret_cast<const int*>(smem + SM_LJ);

    float acc[2][8][4];
    #pragma unroll
    for (int mt = 0; mt < 2; mt++)
        #pragma unroll
        for (int nt = 0; nt < 8; nt++)
            #pragma unroll
            for (int q = 0; q < 4; q++) acc[mt][nt][q] = 0.0f;

    #pragma unroll
    for (int k = 0; k < 8; k++) {
        uint32_t a[2][4];
        #pragma unroll
        for (int mt = 0; mt < 2; mt++) {
            uint32_t addr = SA + (arow + mt * 16) * 256
                          + (((k * 2 + akx) ^ sub) << 4);
            LDSM4(a[mt][0], a[mt][1], a[mt][2], a[mt][3], addr);
        }
        #pragma unroll
        for (int p = 0; p < 4; p++) {
            uint32_t b0, b1, b2, b3;
            uint32_t addr = SB + (brow + p * 16) * 256
                          + (((k * 2 + bkx) ^ sub) << 4);
            LDSM4(b0, b1, b2, b3, addr);
            MMA16816(acc[0][2 * p],     a[0][0], a[0][1], a[0][2], a[0][3], b0, b1);
            MMA16816(acc[0][2 * p + 1], a[0][0], a[0][1], a[0][2], a[0][3], b2, b3);
            MMA16816(acc[1][2 * p],     a[1][0], a[1][1], a[1][2], a[1][3], b0, b1);
            MMA16816(acc[1][2 * p + 1], a[1][0], a[1][1], a[1][2], a[1][3], b2, b3);
        }
    }

    float re[2][2] = {{0, 0}, {0, 0}};
    float rp[2][2] = {{0, 0}, {0, 0}};
    if (diag)
        epilogue<true >(acc, s_lj, s_ce, s_cp, wm, wn, lane, li, re, rp);
    else
        epilogue<false>(acc, s_lj, s_ce, s_cp, wm, wn, lane, li, re, rp);

    // Row side: quad reduce, one atomic pair per row per CTA.
    #pragma unroll
    for (int mt = 0; mt < 2; mt++) {
        #pragma unroll
        for (int h = 0; h < 2; h++) {
            float s = re[mt][h];
            s += __shfl_xor_sync(0xffffffffu, s, 1);
            s += __shfl_xor_sync(0xffffffffu, s, 2);
            float p = rp[mt][h];
            p += __shfl_xor_sync(0xffffffffu, p, 1);
            p += __shfl_xor_sync(0xffffffffu, p, 2);
            if ((lane & 3) == 0) {
                int row = bi * TB + wm * 32 + mt * 16 + h * 8 + (lane >> 2);
                atomicAdd(&g_sumexp[row], s);
                atomicAdd(&g_possum[row], p * 10.0f);
            }
        }
    }

    // Col side: flush smem accumulators to bj's rows (off-diagonal only).
    if (!diag) {
        __syncthreads();
        if (tid < 128) {
            atomicAdd(&g_sumexp[bj * TB + tid], s_ce[tid]);
            atomicAdd(&g_possum[bj * TB + tid], s_cp[tid] * 10.0f);
        }
    }

    // ----- last-CTA fused finish -----
    __shared__ int s_last;
    __threadfence();
    __syncthreads();
    if (tid == 0) {
        int prev = atomicAdd(&g_done, 1);
        s_last = (prev == (int)gridDim.x - 1);
    }
    __syncthreads();
    if (!s_last) return;

    __threadfence();
    __shared__ float fred[8];
    float sum = 0.0f;
    for (int r = tid; r < NN; r += 256) {
        float se  = __ldcg(&g_sumexp[r]);
        float ps  = __ldcg(&g_possum[r]);
        int   cnt = __ldcg(&g_hist[g_lab[r] & 1023]) - 1;
        float L   = __logf(se + 1e-9f);
        sum += (cnt > 0) ? (ps - (float)cnt * L) / (float)cnt : 0.0f;
    }
    #pragma unroll
    for (int o = 16; o > 0; o >>= 1) sum += __shfl_xor_sync(0xffffffffu, sum, o);
    if (lane == 0) fred[wid] = sum;
    __syncthreads();
    if (tid < 8) {
        float s = fred[tid];
        #pragma unroll
        for (int o = 4; o > 0; o >>= 1) s += __shfl_xor_sync(0xffu, s, o);
        if (tid == 0) out[0] = -s / (float)NN;
    }
}

// ---------------------------------------------------------------------------
extern "C" void kernel_launch(void* const* d_in, const int* in_sizes, int n_in,
                              void* d_out, int out_size) {
    const float* feats  = (const float*)d_in[0];
    const void*  labels = d_in[1];
    float* out = (float*)d_out;

    cudaFuncSetAttribute(main_kernel,
                         cudaFuncAttributeMaxDynamicSharedMemorySize, SM_TOT);

    init_kernel<<<32, 256>>>((const int*)labels, out);
    prep_kernel<<<NN / 8, 256>>>(feats, labels);
    main_kernel<<<NTILES, 256, SM_TOT>>>(out);
}

// round 17
// speedup vs baseline: 1.6716x; 1.6716x over previous
#include <cuda_runtime.h>
#include <cuda_bf16.h>
#include <cstdint>

// SupConLoss N=8192, D=128, T=0.1 — mma.sync bf16 (sm_103 base target).
// R17 = R14 main (symmetric single-tile CTAs, 57.9us proven) + separate
// parallel finish. The R15/R16 fused finish is REVERTED: its per-CTA
// __threadfence (gpu scope) emits CCTL.IVALL (L1D flush) in all 2080 CTAs
// and cost ~35us. Init's serial label scan replaced by a 512-sample probe.

static constexpr int NN = 8192;
static constexpr int DD = 128;
static constexpr int TB = 128;            // tile dim
static constexpr int NT = NN / TB;        // 64
static constexpr int NTILES = NT * (NT / 2) + NT / 2; // 2080

__device__ __align__(16) __nv_bfloat16 g_featbf[NN * DD];
__device__ float g_sumexp[NN];
__device__ float g_possum[NN];
__device__ int   g_lab[NN];
__device__ int   g_hist[1024];
__device__ int   g_is64;

// ---------------- PTX helpers (base-target only) -----------------------------
__device__ __forceinline__ uint32_t smem_u32(const void* p) {
    uint32_t a;
    asm("{ .reg .u64 t; cvta.to.shared.u64 t, %1; cvt.u32.u64 %0, t; }"
        : "=r"(a) : "l"(p));
    return a;
}
#define LDSM4(r0, r1, r2, r3, addr) \
    asm volatile("ldmatrix.sync.aligned.m8n8.x4.shared.b16 {%0,%1,%2,%3}, [%4];" \
        : "=r"(r0), "=r"(r1), "=r"(r2), "=r"(r3) : "r"(addr))
#define MMA16816(d, a0, a1, a2, a3, b0, b1) \
    asm volatile("mma.sync.aligned.m16n8k16.row.col.f32.bf16.bf16.f32 " \
        "{%0,%1,%2,%3}, {%4,%5,%6,%7}, {%8,%9}, {%0,%1,%2,%3};" \
        : "+f"((d)[0]), "+f"((d)[1]), "+f"((d)[2]), "+f"((d)[3]) \
        : "r"(a0), "r"(a1), "r"(a2), "r"(a3), "r"(b0), "r"(b1))
#define CP_ASYNC16(sdst, gsrc) \
    asm volatile("cp.async.cg.shared.global [%0], [%1], 16;" \
        :: "r"(sdst), "l"(gsrc) : "memory")
#define CP_COMMIT()  asm volatile("cp.async.commit_group;" ::: "memory")
#define CP_WAIT0()   asm volatile("cp.async.wait_group 0;" ::: "memory")

// ---------------------------------------------------------------------------
// init: zero accumulators; dtype probe samples 512 labels (high words all
// zero <=> little-endian int64; P(false positive | int32 in [0,1000)) ~ 0).
__global__ void init_kernel(const int* __restrict__ labs, float* out) {
    int gid = blockIdx.x * 256 + threadIdx.x;
    if (gid < NN)   { g_sumexp[gid] = 0.0f; g_possum[gid] = 0.0f; }
    if (gid < 1024) g_hist[gid] = 0;
    if (gid == 0)   out[0] = 0.0f;
    if (blockIdx.x == 0) {
        int tid = threadIdx.x;
        int nz = (tid < 256) ? (labs[2 * tid + 1] | labs[2 * (tid + 256) + 1]) : 0;
        #pragma unroll
        for (int o = 16; o > 0; o >>= 1) nz |= __shfl_xor_sync(0xffffffffu, nz, o);
        __shared__ int red[8];
        if ((tid & 31) == 0) red[tid >> 5] = nz;
        __syncthreads();
        if (tid == 0) {
            int r = 0;
            #pragma unroll
            for (int w = 0; w < 8; w++) r |= red[w];
            g_is64 = (r == 0) ? 1 : 0;
        }
    }
}

__global__ void prep_kernel(const float* __restrict__ feats,
                            const void* __restrict__ labels) {
    int row  = blockIdx.x * 8 + (threadIdx.x >> 5);
    int lane = threadIdx.x & 31;
    float4 v = reinterpret_cast<const float4*>(feats)[row * 32 + lane];
    float ss = v.x * v.x + v.y * v.y + v.z * v.z + v.w * v.w;
    #pragma unroll
    for (int o = 16; o > 0; o >>= 1) ss += __shfl_xor_sync(0xffffffffu, ss, o);
    float sc = 1.0f / sqrtf(ss);
    __nv_bfloat162 p0 = __floats2bfloat162_rn(v.x * sc, v.y * sc);
    __nv_bfloat162 p1 = __floats2bfloat162_rn(v.z * sc, v.w * sc);
    uint2 u;
    u.x = *reinterpret_cast<uint32_t*>(&p0);
    u.y = *reinterpret_cast<uint32_t*>(&p1);
    reinterpret_cast<uint2*>(g_featbf)[row * 32 + lane] = u;
    if (lane == 0) {
        int lab = g_is64 ? (int)((const long long*)labels)[row]
                         : ((const int*)labels)[row];
        g_lab[row] = lab;
        atomicAdd(&g_hist[lab & 1023], 1);
    }
}

// ---------------------------------------------------------------------------
// SMEM: A 32KB | B 32KB | col labels 512B | col accumulators 2x512B.
// Rows: 256B K-major, 16B chunks XOR-swizzled with (row & 7).
static constexpr int SM_A   = 0;
static constexpr int SM_B   = 32768;
static constexpr int SM_LJ  = 65536;
static constexpr int SM_CE  = 66048;
static constexpr int SM_CP  = 66560;
static constexpr int SM_TOT = 67072;

__device__ __forceinline__ void cp_tile(uint32_t sdst,
                                        const __nv_bfloat16* gsrc, int tid) {
    #pragma unroll
    for (int i = 0; i < 8; i++) {
        int e   = i * 256 + tid;        // 2048 x 16B
        int row = e >> 4;
        int ch  = e & 15;
        uint32_t off = row * 256 + ((ch ^ (row & 7)) << 4);
        CP_ASYNC16(sdst + off, (const char*)gsrc + (size_t)e * 16);
    }
}

// exp(10*x) = ex2(x * 10*log2(e))
static constexpr float EXSCALE = 14.4269504088896341f;

template <bool DIAG>
__device__ __forceinline__ void epilogue(const float (&acc)[2][8][4],
                                         const int* __restrict__ s_lj,
                                         float* __restrict__ s_ce,
                                         float* __restrict__ s_cp,
                                         int wm, int wn, int lane,
                                         const int (&li)[2][2],
                                         float (&re)[2][2], float (&rp)[2][2]) {
    #pragma unroll
    for (int nt = 0; nt < 8; nt++) {
        int c0  = wn * 64 + nt * 8 + 2 * (lane & 3);
        int lj0 = s_lj[c0], lj1 = s_lj[c0 + 1];
        float ce0 = 0, ce1 = 0, cq0 = 0, cq1 = 0;
        #pragma unroll
        for (int mt = 0; mt < 2; mt++) {
            int r0 = wm * 32 + mt * 16 + (lane >> 2);
            #pragma unroll
            for (int q = 0; q < 4; q++) {
                int   h  = q >> 1;
                float a  = acc[mt][nt][q];
                float x  = a * EXSCALE;
                float e;
                asm("ex2.approx.f32 %0, %1;" : "=f"(e) : "f"(x));
                bool match = (li[mt][h] == ((q & 1) ? lj1 : lj0));
                if (DIAG) {
                    int rl = r0 + h * 8;
                    if (c0 + (q & 1) == rl) { e = 0.0f; match = false; }
                }
                re[mt][h] += e;
                if (match) rp[mt][h] += a;
                if (!DIAG) {
                    if (q & 1) { ce1 += e; if (match) cq1 += a; }
                    else       { ce0 += e; if (match) cq0 += a; }
                }
            }
        }
        if (!DIAG) {
            #pragma unroll
            for (int o = 4; o <= 16; o <<= 1) {
                ce0 += __shfl_xor_sync(0xffffffffu, ce0, o);
                ce1 += __shfl_xor_sync(0xffffffffu, ce1, o);
                cq0 += __shfl_xor_sync(0xffffffffu, cq0, o);
                cq1 += __shfl_xor_sync(0xffffffffu, cq1, o);
            }
            if (lane < 4) {
                int c = wn * 64 + nt * 8 + 2 * lane;
                atomicAdd(&s_ce[c],     ce0);
                atomicAdd(&s_ce[c + 1], ce1);
                atomicAdd(&s_cp[c],     cq0);
                atomicAdd(&s_cp[c + 1], cq1);
            }
        }
    }
}

__global__ void __launch_bounds__(256, 2)
main_kernel() {
    extern __shared__ char smem[];
    uint32_t sb = smem_u32(smem);
    int tid  = threadIdx.x;
    int wid  = tid >> 5, lane = tid & 31;
    int sub  = lane & 7, g = lane >> 3;
    int wm   = wid & 3, wn = wid >> 2;     // 4x2 warp grid (M x N)

    // tile (bi, bj): d=0..31 for all bi, d=32 for bi<32 (upper triangle, once)
    int idx = blockIdx.x;
    int bi, d;
    if (idx < NT * 32) { bi = idx & (NT - 1); d = idx >> 6; }
    else               { bi = idx - NT * 32; d = 32; }
    int bj = (bi + d) & (NT - 1);
    bool diag = (d == 0);

    cp_tile(sb + SM_A, g_featbf + (size_t)bi * TB * DD, tid);
    if (!diag) cp_tile(sb + SM_B, g_featbf + (size_t)bj * TB * DD, tid);
    if (tid < 32) CP_ASYNC16(sb + SM_LJ + tid * 16,
                             (const char*)(g_lab + bj * TB) + tid * 16);
    CP_COMMIT();

    float* s_ce = reinterpret_cast<float*>(smem + SM_CE);
    float* s_cp = reinterpret_cast<float*>(smem + SM_CP);
    if (tid < 128) { s_ce[tid] = 0.0f; s_cp[tid] = 0.0f; }

    int li[2][2];
    #pragma unroll
    for (int mt = 0; mt < 2; mt++)
        #pragma unroll
        for (int h = 0; h < 2; h++)
            li[mt][h] = g_lab[bi * TB + wm * 32 + mt * 16 + h * 8 + (lane >> 2)];

    int arow = wm * 32 + (g & 1) * 8 + sub;          // + mt*16
    int akx  = g >> 1;
    int brow = wn * 64 + (g >> 1) * 8 + sub;         // + p*16
    int bkx  = g & 1;

    CP_WAIT0();
    __syncthreads();

    uint32_t SA = sb + SM_A;
    uint32_t SB = diag ? SA : (sb + SM_B);
    const int* s_lj = reinterpret_cast<const int*>(smem + SM_LJ);

    float acc[2][8][4];
    #pragma unroll
    for (int mt = 0; mt < 2; mt++)
        #pragma unroll
        for (int nt = 0; nt < 8; nt++)
            #pragma unroll
            for (int q = 0; q < 4; q++) acc[mt][nt][q] = 0.0f;

    #pragma unroll
    for (int k = 0; k < 8; k++) {
        uint32_t a[2][4];
        #pragma unroll
        for (int mt = 0; mt < 2; mt++) {
            uint32_t addr = SA + (arow + mt * 16) * 256
                          + (((k * 2 + akx) ^ sub) << 4);
            LDSM4(a[mt][0], a[mt][1], a[mt][2], a[mt][3], addr);
        }
        #pragma unroll
        for (int p = 0; p < 4; p++) {
            uint32_t b0, b1, b2, b3;
            uint32_t addr = SB + (brow + p * 16) * 256
                          + (((k * 2 + bkx) ^ sub) << 4);
            LDSM4(b0, b1, b2, b3, addr);
            MMA16816(acc[0][2 * p],     a[0][0], a[0][1], a[0][2], a[0][3], b0, b1);
            MMA16816(acc[0][2 * p + 1], a[0][0], a[0][1], a[0][2], a[0][3], b2, b3);
            MMA16816(acc[1][2 * p],     a[1][0], a[1][1], a[1][2], a[1][3], b0, b1);
            MMA16816(acc[1][2 * p + 1], a[1][0], a[1][1], a[1][2], a[1][3], b2, b3);
        }
    }

    float re[2][2] = {{0, 0}, {0, 0}};
    float rp[2][2] = {{0, 0}, {0, 0}};
    if (diag)
        epilogue<true >(acc, s_lj, s_ce, s_cp, wm, wn, lane, li, re, rp);
    else
        epilogue<false>(acc, s_lj, s_ce, s_cp, wm, wn, lane, li, re, rp);

    // Row side: quad reduce, one atomic pair per row per CTA.
    #pragma unroll
    for (int mt = 0; mt < 2; mt++) {
        #pragma unroll
        for (int h = 0; h < 2; h++) {
            float s = re[mt][h];
            s += __shfl_xor_sync(0xffffffffu, s, 1);
            s += __shfl_xor_sync(0xffffffffu, s, 2);
            float p = rp[mt][h];
            p += __shfl_xor_sync(0xffffffffu, p, 1);
            p += __shfl_xor_sync(0xffffffffu, p, 2);
            if ((lane & 3) == 0) {
                int row = bi * TB + wm * 32 + mt * 16 + h * 8 + (lane >> 2);
                atomicAdd(&g_sumexp[row], s);
                atomicAdd(&g_possum[row], p * 10.0f);
            }
        }
    }

    // Col side: flush smem accumulators to bj's rows (off-diagonal only).
    if (!diag) {
        __syncthreads();
        if (tid < 128) {
            atomicAdd(&g_sumexp[bj * TB + tid], s_ce[tid]);
            atomicAdd(&g_possum[bj * TB + tid], s_cp[tid] * 10.0f);
        }
    }
}

// ---------------------------------------------------------------------------
// Parallel finish: one row per thread, block partial sums, atomic combine.
__global__ void finish_kernel(float* out) {
    __shared__ float red[8];
    int tid = threadIdx.x;
    int r   = blockIdx.x * 256 + tid;
    float L   = __logf(g_sumexp[r] + 1e-9f);
    int   cnt = g_hist[g_lab[r] & 1023] - 1;
    float c   = (cnt > 0) ? (g_possum[r] - (float)cnt * L) / (float)cnt : 0.0f;
    #pragma unroll
    for (int o = 16; o > 0; o >>= 1) c += __shfl_xor_sync(0xffffffffu, c, o);
    if ((tid & 31) == 0) red[tid >> 5] = c;
    __syncthreads();
    if (tid < 8) {
        float s = red[tid];
        #pragma unroll
        for (int o = 4; o > 0; o >>= 1) s += __shfl_xor_sync(0xffu, s, o);
        if (tid == 0) atomicAdd(out, -s / (float)NN);
    }
}

// ---------------------------------------------------------------------------
extern "C" void kernel_launch(void* const* d_in, const int* in_sizes, int n_in,
                              void* d_out, int out_size) {
    const float* feats  = (const float*)d_in[0];
    const void*  labels = d_in[1];
    float* out = (float*)d_out;

    cudaFuncSetAttribute(main_kernel,
                         cudaFuncAttributeMaxDynamicSharedMemorySize, SM_TOT);

    init_kernel<<<32, 256>>>((const int*)labels, out);
    prep_kernel<<<NN / 8, 256>>>(feats, labels);
    main_kernel<<<NTILES, 256, SM_TOT>>>();
    finish_kernel<<<NN / 256, 256>>>(out);
}